// round 1
// baseline (speedup 1.0000x reference)
#include <cuda_runtime.h>
#include <cstdint>

#define BATCH 16
#define NPTS  9216
#define CH    256
#define KC    21
#define KP    24
#define ITERS 20
#define TILE_N 128
#define XS_STRIDE 260   // words; /4 = 65 (odd) => conflict-free LDS.128/STS.128

// -------- persistent scratch (no allocations allowed) --------
__device__ unsigned long long g_sums[BATCH*KC*CH];   // fixed-point 2^30 accumulators
__device__ int                g_counts[BATCH*KC];
__device__ float              g_cent[BATCH*KC*CH];
__device__ float              g_csq[BATCH*KP];       // 0.5*||c||^2, pads = +inf
__device__ int                g_is64;

__device__ __forceinline__ void fma2(unsigned long long &d, unsigned long long a,
                                     unsigned long long b) {
    asm("fma.rn.f32x2 %0, %1, %2, %0;" : "+l"(d) : "l"(a), "l"(b));
}
__device__ __forceinline__ float2 u2f2(unsigned long long v) {
    float2 f; asm("mov.b64 {%0, %1}, %2;" : "=f"(f.x), "=f"(f.y) : "l"(v)); return f;
}

// -------- detect int32 vs int64 init_idx --------
__global__ void detect_kernel(const unsigned long long* __restrict__ p) {
    __shared__ int any;
    if (threadIdx.x == 0) any = 0;
    __syncthreads();
    int loc = 0;
    for (int i = threadIdx.x; i < (BATCH*KC)/2; i += blockDim.x)  // 168 u64 = 1344B, safe either way
        if ((p[i] >> 32) != 0ull) loc = 1;
    if (loc) atomicExch(&any, 1);
    __syncthreads();
    if (threadIdx.x == 0) g_is64 = (any == 0) ? 1 : 0;
}

// -------- gather initial centroids + reset state --------
__global__ void __launch_bounds__(256)
gather_kernel(const float* __restrict__ x, const void* __restrict__ ip) {
    const int k = blockIdx.x, b = blockIdx.y;
    if (k >= KC) {
        if (threadIdx.x == 0) g_csq[b*KP + k] = __int_as_float(0x7f800000);
        return;
    }
    const int bi = b*KC + k;
    long long idx;
    if (g_is64) idx = ((const long long*)ip)[bi];
    else        idx = (long long)((const int*)ip)[bi];
    float v = x[((size_t)b*NPTS + (size_t)idx)*CH + threadIdx.x];
    const int i = bi*CH + threadIdx.x;
    g_cent[i] = v;
    g_sums[i] = 0ull;

    float sq = v*v;
    #pragma unroll
    for (int o = 16; o > 0; o >>= 1) sq += __shfl_xor_sync(0xffffffffu, sq, o);
    __shared__ float ws[8];
    if ((threadIdx.x & 31) == 0) ws[threadIdx.x >> 5] = sq;
    __syncthreads();
    if (threadIdx.x == 0) {
        float t = 0.f;
        #pragma unroll
        for (int w = 0; w < 8; w++) t += ws[w];
        g_csq[b*KP + k] = 0.5f * t;
        g_counts[bi] = 0;
    }
}

// -------- fused assignment + accumulation --------
__global__ void __launch_bounds__(128, 1)
assign_kernel(const float* __restrict__ x) {
    extern __shared__ float sm[];
    float* x_s    = sm;                            // 128*260
    float* cent_s = sm + TILE_N*XS_STRIDE;         // 24*256
    float* csq_s  = cent_s + KP*CH;                // 24
    float* bins   = csq_s + KP;                    // 21*256
    float* cnt_s  = bins + KC*CH;                  // 24
    float* red_s  = cnt_s + KP;                    // 4*128
    int*   red_k  = (int*)(red_s + 4*TILE_N);      // 4*128
    int*   asg    = red_k + 4*TILE_N;              // 128

    const int tid = threadIdx.x;
    const int b   = blockIdx.y;
    const int n0  = blockIdx.x * TILE_N;
    const float* xb = x + ((size_t)b*NPTS + n0)*CH;

    // ---- load x tile: coalesced LDG.128, conflict-free STS.128 ----
    #pragma unroll 4
    for (int it = 0; it < 64; ++it) {
        int idx = it*128 + tid;
        int n  = idx >> 6;
        int cq = idx & 63;
        float4 v = *(const float4*)(xb + n*CH + (cq << 2));
        *(float4*)(x_s + n*XS_STRIDE + (cq << 2)) = v;
    }
    for (int t = tid; t < KP*CH; t += 128) {
        int k = t >> 8;
        cent_s[t] = (k < KC) ? g_cent[(b*KC + k)*CH + (t & 255)] : 0.0f;
    }
    if (tid < KP) csq_s[tid] = g_csq[b*KP + tid];
    for (int t = tid; t < KC*CH; t += 128) bins[t] = 0.0f;
    if (tid < KP) cnt_s[tid] = 0.0f;
    __syncthreads();

    // ---- dot products: TN=4 points x TK=6 clusters, packed f32x2 ----
    const int pg = tid & 31;
    const int kg = tid >> 5;
    const int k0 = kg * 6;

    unsigned long long acc[4][6][2];
    #pragma unroll
    for (int i = 0; i < 4; i++)
        #pragma unroll
        for (int j = 0; j < 6; j++) { acc[i][j][0] = 0ull; acc[i][j][1] = 0ull; }

    #pragma unroll 2
    for (int cq = 0; cq < CH/4; ++cq) {
        ulonglong2 cv[6];
        #pragma unroll
        for (int j = 0; j < 6; j++)
            cv[j] = *(const ulonglong2*)(cent_s + (k0 + j)*CH + (cq << 2));
        #pragma unroll
        for (int i = 0; i < 4; i++) {
            ulonglong2 xq = *(const ulonglong2*)(x_s + (pg + (i << 5))*XS_STRIDE + (cq << 2));
            #pragma unroll
            for (int j = 0; j < 6; j++) {
                fma2(acc[i][j][0], xq.x, cv[j].x);
                fma2(acc[i][j][1], xq.y, cv[j].y);
            }
        }
    }

    // ---- local argmin (ascending k, strict <) ----
    const float INF = __int_as_float(0x7f800000);
    #pragma unroll
    for (int i = 0; i < 4; i++) {
        float bs = INF; int bk = k0;
        #pragma unroll
        for (int j = 0; j < 6; j++) {
            float2 a0 = u2f2(acc[i][j][0]);
            float2 a1 = u2f2(acc[i][j][1]);
            float dot = (a0.x + a0.y) + (a1.x + a1.y);
            float s = csq_s[k0 + j] - dot;   // 0.5||c||^2 - x.c  (x^2 const)
            if (s < bs) { bs = s; bk = k0 + j; }
        }
        red_s[kg*TILE_N + pg + (i << 5)] = bs;
        red_k[kg*TILE_N + pg + (i << 5)] = bk;
    }
    __syncthreads();

    // ---- cross-group reduce (ascending group => first-index tiebreak) ----
    {
        int n = tid;
        float bs = red_s[n]; int bk = red_k[n];
        #pragma unroll
        for (int g = 1; g < 4; ++g) {
            float s = red_s[g*TILE_N + n];
            if (s < bs) { bs = s; bk = red_k[g*TILE_N + n]; }
        }
        asg[n] = bk;
        atomicAdd(&cnt_s[bk], 1.0f);
    }
    __syncthreads();

    // ---- block-local bins (each thread owns channels tid, tid+128) ----
    for (int i = 0; i < TILE_N; ++i) {
        int a = asg[i];
        bins[a*CH + tid]       += x_s[i*XS_STRIDE + tid];
        bins[a*CH + tid + 128] += x_s[i*XS_STRIDE + tid + 128];
    }
    // flush own channels: fixed-point atomics => deterministic
    for (int t = tid; t < KC*CH; t += 128) {
        long long q = llrintf(bins[t] * 1073741824.0f);   // 2^30
        atomicAdd(&g_sums[b*KC*CH + t], (unsigned long long)q);
    }
    if (tid < KC) atomicAdd(&g_counts[b*KC + tid], __float2int_rn(cnt_s[tid]));
}

// -------- scatter-mean + csq for next iter; last iter writes d_out --------
__global__ void __launch_bounds__(256)
finalize_kernel(float* __restrict__ out, int write_out) {
    const int k = blockIdx.x, b = blockIdx.y;
    const int bi = b*KC + k;
    const int i  = bi*CH + threadIdx.x;
    int cnt = g_counts[bi];
    float v;
    if (cnt > 0) {
        float s = (float)(long long)g_sums[i] * 9.313225746154785e-10f; // 2^-30
        v = s / (float)cnt;
    } else {
        v = g_cent[i];          // empty cluster keeps previous centroid
    }
    g_cent[i] = v;
    if (write_out) out[i] = v;
    g_sums[i] = 0ull;

    float sq = v*v;
    #pragma unroll
    for (int o = 16; o > 0; o >>= 1) sq += __shfl_xor_sync(0xffffffffu, sq, o);
    __shared__ float ws[8];
    if ((threadIdx.x & 31) == 0) ws[threadIdx.x >> 5] = sq;
    __syncthreads();
    if (threadIdx.x == 0) {
        float t = 0.f;
        #pragma unroll
        for (int w = 0; w < 8; w++) t += ws[w];
        g_csq[b*KP + k] = 0.5f * t;
        g_counts[bi] = 0;
    }
}

extern "C" void kernel_launch(void* const* d_in, const int* in_sizes, int n_in,
                              void* d_out, int out_size) {
    const float* x  = (const float*)d_in[0];
    const void*  ip = d_in[1];
    float* out = (float*)d_out;

    const int SMEM = (TILE_N*XS_STRIDE + KP*CH + KP + KC*CH + KP + 4*TILE_N)*4
                     + 4*TILE_N*4 + TILE_N*4;   // 184000 bytes
    cudaFuncSetAttribute(assign_kernel, cudaFuncAttributeMaxDynamicSharedMemorySize, SMEM);

    detect_kernel<<<1, 256>>>((const unsigned long long*)ip);
    gather_kernel<<<dim3(KP, BATCH), 256>>>(x, ip);
    for (int it = 0; it < ITERS; ++it) {
        assign_kernel<<<dim3(NPTS/TILE_N, BATCH), 128, SMEM>>>(x);
        finalize_kernel<<<dim3(KC, BATCH), 256>>>(out, it == ITERS-1 ? 1 : 0);
    }
}

// round 2
// speedup vs baseline: 2.1942x; 2.1942x over previous
#include <cuda_runtime.h>
#include <cstdint>

#define BATCH 16
#define NPTS  9216
#define CH    256
#define KC    21
#define KP    24
#define ITERS 20
#define SUB   64
#define XS    260          // floats per point row; /4 = 65 odd => conflict-free LDS.128
#define THREADS 128
#define MAXCTA 288

// ---------------- persistent device state (no allocations allowed) ----------------
__device__ float g_cent[BATCH*KC*CH];
__device__ float g_csq[BATCH*KC];
__device__ float g_part[MAXCTA*KC*CH];
__device__ int   g_pcnt[MAXCTA*KC];
__device__ unsigned int g_bar_cnt;
__device__ volatile unsigned int g_bar_gen;

__device__ __forceinline__ void fma2(unsigned long long &d, unsigned long long a,
                                     unsigned long long b) {
    asm("fma.rn.f32x2 %0, %1, %2, %0;" : "+l"(d) : "l"(a), "l"(b));
}
__device__ __forceinline__ void add2(unsigned long long &d, unsigned long long a) {
    asm("add.rn.f32x2 %0, %0, %1;" : "+l"(d) : "l"(a));
}
__device__ __forceinline__ float2 u2f2(unsigned long long v) {
    float2 f; asm("mov.b64 {%0, %1}, %2;" : "=f"(f.x), "=f"(f.y) : "l"(v)); return f;
}

// grid-wide barrier: generation counter, replay-safe (gen only ever increases)
__device__ __forceinline__ void gridbar(unsigned nct) {
    __syncthreads();
    if (threadIdx.x == 0) {
        unsigned g = g_bar_gen;
        __threadfence();
        unsigned a = atomicAdd(&g_bar_cnt, 1u);
        if (a == nct - 1u) {
            g_bar_cnt = 0u;
            __threadfence();
            g_bar_gen = g + 1u;
        } else {
            while (g_bar_gen == g) { __nanosleep(64); }
        }
        __threadfence();
    }
    __syncthreads();
}

// async-copy one 64-point subtile (64KB) into padded smem layout
__device__ __forceinline__ void cp_subtile(const float* __restrict__ xb,
                                           float* x_s, int st, int tid) {
    const float* src = xb + (size_t)st*SUB*CH;
    unsigned sbase = (unsigned)__cvta_generic_to_shared(x_s);
    #pragma unroll
    for (int l = 0; l < (SUB*CH/4)/THREADS; ++l) {   // 32 x 16B per thread
        int idx = l*THREADS + tid;
        int n = idx >> 6, cq = idx & 63;
        unsigned dst = sbase + (unsigned)((n*XS + cq*4)*4);
        const float* s = src + n*CH + cq*4;
        asm volatile("cp.async.cg.shared.global [%0], [%1], 16;" :: "r"(dst), "l"(s));
    }
    asm volatile("cp.async.commit_group;" ::: "memory");
}

extern "C" __global__ void __launch_bounds__(THREADS, 2)
kmeans_persist(const float* __restrict__ x, const void* __restrict__ ip,
               float* __restrict__ out, int cpb) {
    extern __shared__ float sm[];
    float* x_s   = sm;                    // 16640 f
    float* cent  = x_s + SUB*XS;          // 5376 f  (rows 21..23 overflow into bins: NaN/inf-safe)
    float* bins  = cent + KC*CH;          // 5376 f
    float* red_s = bins + KC*CH;          // 256 f
    float* csq_s = red_s + 4*SUB;         // 32 f
    float* cnt_s = csq_s + 32;            // 32 f
    int*   red_k = (int*)(cnt_s + 32);    // 256 i
    int*   asg   = red_k + 4*SUB;         // 64 i
    int*   flag  = asg + SUB;             // 8 i

    const unsigned nct = gridDim.x;
    const int bid = blockIdx.x;
    const int tid = threadIdx.x;
    const int b     = bid / cpb;
    const int chunk = bid % cpb;
    const int ppc   = NPTS / cpb;
    const int nsub  = ppc / SUB;
    const float* xb = x + ((size_t)b*NPTS + (size_t)chunk*ppc)*CH;

    const int lane = tid & 31;
    const int kg   = tid >> 5;
    const int k0   = kg * 6;
    unsigned long long* x_u   = (unsigned long long*)x_s;
    unsigned long long* bin_u = (unsigned long long*)bins;
    const float INF = __int_as_float(0x7f800000);

    // ---- int64 vs int32 init_idx detection (local, per CTA) ----
    if (tid == 0) {
        const unsigned long long* p = (const unsigned long long*)ip;
        int any = 0;
        #pragma unroll 8
        for (int i = 0; i < (BATCH*KC)/2; ++i) any |= ((p[i] >> 32) != 0ull);
        flag[0] = any ? 0 : 1;   // 1 => int64
    }
    __syncthreads();
    const int is64 = flag[0];

    // ---- init: gather initial centroids + 0.5*||c||^2 ----
    for (int task = bid; task < BATCH*KC; task += nct) {
        int tb = task / KC;
        long long idx = is64 ? ((const long long*)ip)[task]
                             : (long long)((const int*)ip)[task];
        const float* src = x + ((size_t)tb*NPTS + (size_t)idx)*CH;
        float v0 = src[tid], v1 = src[tid+128];
        g_cent[task*CH + tid]       = v0;
        g_cent[task*CH + tid + 128] = v1;
        float sq = v0*v0 + v1*v1;
        #pragma unroll
        for (int o = 16; o > 0; o >>= 1) sq += __shfl_xor_sync(~0u, sq, o);
        if ((tid & 31) == 0) red_s[tid >> 5] = sq;
        __syncthreads();
        if (tid == 0) g_csq[task] = 0.5f*(red_s[0]+red_s[1]+red_s[2]+red_s[3]);
        __syncthreads();
    }
    gridbar(nct);

    // ---------------- main iteration loop ----------------
    for (int it = 0; it < ITERS; ++it) {
        cp_subtile(xb, x_s, 0, tid);     // prefetch subtile 0 under cent load
        for (int t = tid; t < KC*CH/4; t += THREADS)
            ((float4*)cent)[t] = ((const float4*)(g_cent + (size_t)b*KC*CH))[t];
        if (tid < KP) csq_s[tid] = (tid < KC) ? g_csq[b*KC + tid] : INF;
        for (int t = tid; t < KC*CH/2; t += THREADS) bin_u[t] = 0ull;
        if (tid < KP) cnt_s[tid] = 0.f;
        __syncthreads();

        for (int st = 0; st < nsub; ++st) {
            asm volatile("cp.async.wait_group 0;" ::: "memory");
            __syncthreads();

            // ---- dots: TN=2 points x TK=6 clusters, packed f32x2 ----
            unsigned long long acc[2][6][2];
            #pragma unroll
            for (int i = 0; i < 2; ++i)
                #pragma unroll
                for (int j = 0; j < 6; ++j) { acc[i][j][0] = 0ull; acc[i][j][1] = 0ull; }

            #pragma unroll 2
            for (int cq = 0; cq < CH/4; ++cq) {
                ulonglong2 cv[6];
                #pragma unroll
                for (int j = 0; j < 6; ++j)
                    cv[j] = *(const ulonglong2*)(cent + (k0+j)*CH + (cq<<2));
                #pragma unroll
                for (int i = 0; i < 2; ++i) {
                    ulonglong2 xq = *(const ulonglong2*)(x_s + (lane + (i<<5))*XS + (cq<<2));
                    #pragma unroll
                    for (int j = 0; j < 6; ++j) {
                        fma2(acc[i][j][0], xq.x, cv[j].x);
                        fma2(acc[i][j][1], xq.y, cv[j].y);
                    }
                }
            }

            // ---- local argmin (ascending k, strict <) ----
            #pragma unroll
            for (int i = 0; i < 2; ++i) {
                float bs = INF; int bk = 0;
                #pragma unroll
                for (int j = 0; j < 6; ++j) {
                    float2 a0 = u2f2(acc[i][j][0]);
                    float2 a1 = u2f2(acc[i][j][1]);
                    float dot = (a0.x+a0.y)+(a1.x+a1.y);
                    float s = csq_s[k0+j] - dot;   // 0.5||c||^2 - x.c
                    if (s < bs) { bs = s; bk = k0+j; }
                }
                red_s[kg*SUB + lane + (i<<5)] = bs;
                red_k[kg*SUB + lane + (i<<5)] = bk;
            }
            __syncthreads();

            // ---- cross-group reduce (ascending kg => first-index tiebreak) ----
            if (tid < SUB) {
                float bs = red_s[tid]; int bk = red_k[tid];
                #pragma unroll
                for (int g2 = 1; g2 < 4; ++g2) {
                    float s2 = red_s[g2*SUB + tid];
                    if (s2 < bs) { bs = s2; bk = red_k[g2*SUB + tid]; }
                }
                asg[tid] = bk;
                atomicAdd(&cnt_s[bk], 1.0f);   // integer-valued: exact, order-independent
            }
            __syncthreads();

            // ---- bins accumulate: thread owns channel pair (f32x2) ----
            for (int i = 0; i < SUB; ++i) {
                int a = asg[i];
                unsigned long long t = bin_u[a*(CH/2) + tid];
                add2(t, x_u[i*(XS/2) + tid]);
                bin_u[a*(CH/2) + tid] = t;
            }
            __syncthreads();

            if (st + 1 < nsub) cp_subtile(xb, x_s, st+1, tid);
        }

        // ---- write per-CTA partials (plain stores, deterministic) ----
        for (int t = tid; t < KC*CH/2; t += THREADS)
            ((unsigned long long*)(g_part + (size_t)bid*KC*CH))[t] = bin_u[t];
        if (tid < KC) g_pcnt[bid*KC + tid] = __float2int_rn(cnt_s[tid]);
        gridbar(nct);

        // ---- finalize: fixed-order reduction over chunks ----
        for (int task = bid; task < BATCH*KC; task += nct) {
            int tb = task / KC, tk = task % KC;
            float s0 = 0.f, s1 = 0.f; int cnt = 0;
            for (int c = 0; c < cpb; ++c) {
                const float* pp = g_part + ((size_t)(tb*cpb + c)*KC + tk)*CH;
                s0 += pp[tid]; s1 += pp[tid+128];
                cnt += g_pcnt[(tb*cpb + c)*KC + tk];
            }
            float v0, v1;
            if (cnt > 0) { v0 = s0 / (float)cnt; v1 = s1 / (float)cnt; }
            else { v0 = g_cent[task*CH+tid]; v1 = g_cent[task*CH+tid+128]; }
            g_cent[task*CH+tid]     = v0;
            g_cent[task*CH+tid+128] = v1;
            if (it == ITERS-1) { out[task*CH+tid] = v0; out[task*CH+tid+128] = v1; }
            float sq = v0*v0 + v1*v1;
            #pragma unroll
            for (int o = 16; o > 0; o >>= 1) sq += __shfl_xor_sync(~0u, sq, o);
            if ((tid & 31) == 0) red_s[tid >> 5] = sq;
            __syncthreads();
            if (tid == 0) g_csq[task] = 0.5f*(red_s[0]+red_s[1]+red_s[2]+red_s[3]);
            __syncthreads();
        }
        gridbar(nct);
    }
}

extern "C" void kernel_launch(void* const* d_in, const int* in_sizes, int n_in,
                              void* d_out, int out_size) {
    const float* x  = (const float*)d_in[0];
    const void*  ip = d_in[1];
    float* out = (float*)d_out;

    const int smem_bytes = (SUB*XS + KC*CH + KC*CH + 4*SUB + 32 + 32)*4
                         + (4*SUB + SUB + 8)*4;     // 112160 B
    cudaFuncSetAttribute(kmeans_persist, cudaFuncAttributeMaxDynamicSharedMemorySize, smem_bytes);

    int occ = 0;
    cudaOccupancyMaxActiveBlocksPerMultiprocessor(&occ, kmeans_persist, THREADS, smem_bytes);
    int sms = 0;
    cudaDeviceGetAttribute(&sms, cudaDevAttrMultiProcessorCount, 0);

    int cpb, grid;
    if (occ >= 2 && sms*2 >= 288) { cpb = 18; grid = 288; }   // 2 CTAs/SM
    else                          { cpb = 9;  grid = 144; }   // safe fallback, 1 CTA/SM

    kmeans_persist<<<grid, THREADS, smem_bytes>>>(x, ip, out, cpb);
}